// round 11
// baseline (speedup 1.0000x reference)
#include <cuda_runtime.h>
#include <cuda_fp16.h>
#include <cstdint>

#define D      128      // D_IN = D_OUT
#define NMAX   100000

// Scratch (device globals; no allocation allowed)
__device__ __half g_xh[NMAX * D];   // x rounded to fp16 (GEMM A operand)
__device__ float  g_y [NMAX * D];   // y = x @ W2 (fp32)

// ============================================================================
// PTX helpers (base ISA: cp.async / ldmatrix / mma.sync)
// ============================================================================
__device__ __forceinline__ uint32_t smem_to_u32(const void* p) {
    uint32_t a;
    asm("{ .reg .u64 t; cvta.to.shared.u64 t, %1; cvt.u32.u64 %0, t; }"
        : "=r"(a) : "l"(p));
    return a;
}
#define CP_ASYNC16(dst, src, sz) \
    asm volatile("cp.async.cg.shared.global [%0], [%1], 16, %2;" \
        :: "r"(dst), "l"(src), "r"(sz))
#define CP_COMMIT() asm volatile("cp.async.commit_group;" ::: "memory")
#define CP_WAIT1()  asm volatile("cp.async.wait_group 1;"  ::: "memory")

#define LDSM_X4(r0,r1,r2,r3,addr) \
    asm volatile("ldmatrix.sync.aligned.m8n8.x4.shared.b16 {%0,%1,%2,%3}, [%4];" \
        : "=r"(r0), "=r"(r1), "=r"(r2), "=r"(r3) : "r"(addr))
#define LDSM_X4T(r0,r1,r2,r3,addr) \
    asm volatile("ldmatrix.sync.aligned.m8n8.x4.trans.shared.b16 {%0,%1,%2,%3}, [%4];" \
        : "=r"(r0), "=r"(r1), "=r"(r2), "=r"(r3) : "r"(addr))

// fp16 inputs, fp32 accumulate
#define MMA16816F16(c, a, b) \
    asm volatile("mma.sync.aligned.m16n8k16.row.col.f32.f16.f16.f32 " \
        "{%0,%1,%2,%3}, {%4,%5,%6,%7}, {%8,%9}, {%0,%1,%2,%3};" \
        : "+f"((c)[0]), "+f"((c)[1]), "+f"((c)[2]), "+f"((c)[3]) \
        : "r"((a)[0]), "r"((a)[1]), "r"((a)[2]), "r"((a)[3]), \
          "r"((b)[0]), "r"((b)[1]))

// ============================================================================
// Kernel 1: round x -> fp16 AND zero d_out (REDs accumulate into it later)
// ============================================================================
__global__ void convert_kernel(const float* __restrict__ x,
                               float* __restrict__ out, int n4) {
    int i = blockIdx.x * blockDim.x + threadIdx.x;
    if (i >= n4) return;
    float4 v = reinterpret_cast<const float4*>(x)[i];
    __half2 h0 = __floats2half2_rn(v.x, v.y);
    __half2 h1 = __floats2half2_rn(v.z, v.w);
    reinterpret_cast<uint2*>(g_xh)[i] =
        make_uint2(*(uint32_t*)&h0, *(uint32_t*)&h1);
    reinterpret_cast<float4*>(out)[i] = make_float4(0.f, 0.f, 0.f, 0.f);
}

// ============================================================================
// GEMM core (R7-proven shape): C = A @ W[nh] with 2-term fp16 split.
//   NH selects the W half. EPI: 0 -> plain fp32 store (g_y),
//                               1 -> red.global.add.v2 of (acc + bias) into out
// ============================================================================
#define GT 256
#define AS_OFF(buf)  ((uint32_t)((buf) * 32768))
#define BS_OFF(hl)   ((uint32_t)(65536 + (hl) * 32768))
#define SM_TOTAL     131072

__device__ __forceinline__ void load_A_tile(uint32_t smem_base, int buf,
                                            int node0, int N, int tid) {
#pragma unroll
    for (int i = 0; i < 8; i++) {
        int idx  = tid + (i << 8);
        int row  = idx >> 4;
        int cc   = idx & 15;
        int node = node0 + row;
        uint32_t sz    = (node < N) ? 16u : 0u;
        uint32_t chunk = (uint32_t)(cc ^ (row & 7));
        uint32_t doff  = (uint32_t)row * 256u + chunk * 16u;
        const __half* sh = g_xh + (size_t)node * D + cc * 8;
        CP_ASYNC16(smem_base + AS_OFF(buf) + doff, sh, sz);
    }
}

template <int NH, int EPI>
__device__ __forceinline__ void gemm_body(const float* __restrict__ W,
                                          const float* __restrict__ bias,
                                          float* __restrict__ dst, int N) {
    extern __shared__ char smem[];
    uint32_t smem_base = smem_to_u32(smem);
    const int tid  = threadIdx.x;
    const int lane = tid & 31;
    const int wid  = tid >> 5;
    const int warp_m = (wid & 3) << 5;
    const int warp_n = (wid >> 2) << 6;
    const int num_tiles = (N + 127) >> 7;

    // B = W[NH*128 : +128][:] split into fp16 hi/lo
#pragma unroll
    for (int j = 0; j < 32; j++) {
        int idx = tid + (j << 8);
        int k   = idx >> 6;
        int n   = (idx & 63) << 1;
        const float* wp = W + ((size_t)(NH * 128 + k)) * 128 + n;
        float w0 = wp[0], w1 = wp[1];
        __half2 h = __floats2half2_rn(w0, w1);
        float q0 = w0 - __half2float(__low2half(h));
        float q1 = w1 - __half2float(__high2half(h));
        __half2 l = __floats2half2_rn(q0, q1);
        uint32_t boff = (uint32_t)k * 256u
                      + (uint32_t)(((n >> 3) ^ (k & 7)) << 4)
                      + (uint32_t)((n & 7) << 1);
        *reinterpret_cast<uint32_t*>(smem + BS_OFF(0) + boff) = *(uint32_t*)&h;
        *reinterpret_cast<uint32_t*>(smem + BS_OFF(1) + boff) = *(uint32_t*)&l;
    }

    int item = blockIdx.x;
    int buf = 0;
    if (item < num_tiles) load_A_tile(smem_base, 0, item << 7, N, tid);
    CP_COMMIT();

    for (; item < num_tiles; item += gridDim.x) {
        const int node0 = item << 7;
        int next = item + gridDim.x;
        if (next < num_tiles) load_A_tile(smem_base, buf ^ 1, next << 7, N, tid);
        CP_COMMIT();
        CP_WAIT1();
        __syncthreads();

        float acc[2][8][4];
#pragma unroll
        for (int mi = 0; mi < 2; mi++)
#pragma unroll
            for (int ni = 0; ni < 8; ni++)
#pragma unroll
                for (int q = 0; q < 4; q++) acc[mi][ni][q] = 0.f;

#pragma unroll
        for (int ks = 0; ks < 8; ks++) {
            uint32_t ah[2][4];
#pragma unroll
            for (int mi = 0; mi < 2; mi++) {
                int row = warp_m + (mi << 4) + (lane & 15);
                int cb  = (ks << 1) + (lane >> 4);
                uint32_t addr = smem_base + AS_OFF(buf)
                              + (uint32_t)row * 256u
                              + (uint32_t)((cb ^ (row & 7)) << 4);
                LDSM_X4(ah[mi][0], ah[mi][1], ah[mi][2], ah[mi][3], addr);
            }
            uint32_t bh[8][2], bl[8][2];
#pragma unroll
            for (int nj = 0; nj < 4; nj++) {
                int row = (ks << 4) + (lane & 15);
                int cb  = (warp_n >> 3) + (nj << 1) + (lane >> 4);
                uint32_t addr = smem_base + BS_OFF(0)
                              + (uint32_t)row * 256u
                              + (uint32_t)((cb ^ (row & 7)) << 4);
                LDSM_X4T(bh[2*nj][0], bh[2*nj][1], bh[2*nj+1][0], bh[2*nj+1][1], addr);
                LDSM_X4T(bl[2*nj][0], bl[2*nj][1], bl[2*nj+1][0], bl[2*nj+1][1],
                         addr + 32768u);
            }
#pragma unroll
            for (int mi = 0; mi < 2; mi++)
#pragma unroll
                for (int ni = 0; ni < 8; ni++) {
                    MMA16816F16(acc[mi][ni], ah[mi], bh[ni]);
                    MMA16816F16(acc[mi][ni], ah[mi], bl[ni]);
                }
        }

#pragma unroll
        for (int ni = 0; ni < 8; ni++) {
            int col = warp_n + (ni << 3) + ((lane & 3) << 1);
            float b0 = 0.f, b1 = 0.f;
            if (EPI == 1) { b0 = bias[col]; b1 = bias[col + 1]; }
#pragma unroll
            for (int mi = 0; mi < 2; mi++) {
#pragma unroll
                for (int half = 0; half < 2; half++) {
                    int node = node0 + warp_m + (mi << 4) + (lane >> 2) + half * 8;
                    if (node < N) {
                        float v0 = acc[mi][ni][half * 2 + 0] + b0;
                        float v1 = acc[mi][ni][half * 2 + 1] + b1;
                        float* p = dst + (size_t)node * D + col;
                        if (EPI == 0) {
                            *reinterpret_cast<float2*>(p) = make_float2(v0, v1);
                        } else {
                            asm volatile(
                                "red.global.add.v2.f32 [%0], {%1, %2};"
                                :: "l"(p), "f"(v0), "f"(v1) : "memory");
                        }
                    }
                }
            }
        }
        __syncthreads();
        buf ^= 1;
    }
}

__global__ __launch_bounds__(GT, 1)
void gemm_y_kernel(const float* __restrict__ W, int N) {
    gemm_body<1, 0>(W, nullptr, g_y, N);
}
__global__ __launch_bounds__(GT, 1)
void gemm_out_kernel(const float* __restrict__ W,
                     const float* __restrict__ bias,
                     float* __restrict__ out, int N) {
    gemm_body<0, 1>(W, bias, out, N);
}

// ============================================================================
// Kernel: edge scatter (warp per edge — proven shape):
//   out[dst] += val * y[src]  via red.global.add.v4.f32
// ============================================================================
__global__ void scatter_kernel(const int*   __restrict__ esrc,
                               const int*   __restrict__ edst,
                               const float* __restrict__ eval_,
                               float* __restrict__ out,
                               int E) {
    int warp = (blockIdx.x * blockDim.x + threadIdx.x) >> 5;
    int lane = threadIdx.x & 31;
    if (warp >= E) return;

    int   s = esrc[warp];
    int   d = edst[warp];
    float v = eval_[warp];

    const float4* ys = reinterpret_cast<const float4*>(g_y) + (size_t)s * (D / 4);
    float4 yv = ys[lane];

    float* p = out + (size_t)d * D + lane * 4;
    asm volatile("red.global.add.v4.f32 [%0], {%1, %2, %3, %4};"
                 :: "l"(p), "f"(yv.x * v), "f"(yv.y * v),
                    "f"(yv.z * v), "f"(yv.w * v)
                 : "memory");
}

// ============================================================================
// Launch: convert -> gemm_y -> [ scatter (main stream) || gemm_out (side) ]
// ============================================================================
extern "C" void kernel_launch(void* const* d_in, const int* in_sizes, int n_in,
                              void* d_out, int out_size) {
    const float* x     = (const float*)d_in[0];
    const int*   esrc  = (const int*)  d_in[1];
    const int*   edst  = (const int*)  d_in[2];
    const float* eval_ = (const float*)d_in[3];
    const float* W     = (const float*)d_in[4];
    const float* bias  = (const float*)d_in[5];
    float*       out   = (float*)d_out;

    const int N = in_sizes[0] / D;     // 100000
    const int E = in_sizes[1];         // 1600000

    static cudaStream_t s1 = nullptr;
    static cudaEvent_t  evFork = nullptr, evJoin = nullptr;
    if (s1 == nullptr) {               // first (uncaptured correctness) call
        cudaStreamCreateWithFlags(&s1, cudaStreamNonBlocking);
        cudaEventCreateWithFlags(&evFork, cudaEventDisableTiming);
        cudaEventCreateWithFlags(&evJoin, cudaEventDisableTiming);
        cudaFuncSetAttribute(gemm_y_kernel,
                             cudaFuncAttributeMaxDynamicSharedMemorySize, SM_TOTAL);
        cudaFuncSetAttribute(gemm_out_kernel,
                             cudaFuncAttributeMaxDynamicSharedMemorySize, SM_TOTAL);
    }

    // 1) round x -> fp16 ; zero out
    {
        int n4 = N * (D / 4);
        convert_kernel<<<(n4 + 255) / 256, 256>>>(x, out, n4);
    }
    // 2) gemm_y: g_y = x @ W2   (main stream)
    gemm_y_kernel<<<148, GT, SM_TOTAL>>>(W, N);

    // 3) fork: gemm_out on side stream, scatter on main stream — both RED
    //    into the zeroed out buffer, so they commute.
    cudaEventRecord(evFork, 0);
    cudaStreamWaitEvent(s1, evFork, 0);
    gemm_out_kernel<<<148, GT, SM_TOTAL, s1>>>(W, bias, out, N);
    {
        int blocks = (E + 7) / 8;      // 8 warps (256 thr) per block
        scatter_kernel<<<blocks, 256>>>(esrc, edst, eval_, out, E);
    }
    // join
    cudaEventRecord(evJoin, s1);
    cudaStreamWaitEvent(0, evJoin, 0);
}

// round 12
// speedup vs baseline: 1.2010x; 1.2010x over previous
#include <cuda_runtime.h>
#include <cuda_fp16.h>
#include <cstdint>

#define D      128      // D_IN = D_OUT
#define NMAX   100000

// Scratch (device globals; no allocation allowed)
__device__ __half g_xh[NMAX * D];   // x rounded to fp16 (GEMM A operand)
__device__ __half g_yh[NMAX * D];   // y = x @ W2, stored fp16

// ============================================================================
// PTX helpers (base ISA: cp.async / ldmatrix / mma.sync / cp.reduce.async.bulk)
// ============================================================================
__device__ __forceinline__ uint32_t smem_to_u32(const void* p) {
    uint32_t a;
    asm("{ .reg .u64 t; cvta.to.shared.u64 t, %1; cvt.u32.u64 %0, t; }"
        : "=r"(a) : "l"(p));
    return a;
}
#define CP_ASYNC16(dst, src, sz) \
    asm volatile("cp.async.cg.shared.global [%0], [%1], 16, %2;" \
        :: "r"(dst), "l"(src), "r"(sz))
#define CP_COMMIT() asm volatile("cp.async.commit_group;" ::: "memory")
#define CP_WAIT1()  asm volatile("cp.async.wait_group 1;"  ::: "memory")

#define LDSM_X4(r0,r1,r2,r3,addr) \
    asm volatile("ldmatrix.sync.aligned.m8n8.x4.shared.b16 {%0,%1,%2,%3}, [%4];" \
        : "=r"(r0), "=r"(r1), "=r"(r2), "=r"(r3) : "r"(addr))
#define LDSM_X4T(r0,r1,r2,r3,addr) \
    asm volatile("ldmatrix.sync.aligned.m8n8.x4.trans.shared.b16 {%0,%1,%2,%3}, [%4];" \
        : "=r"(r0), "=r"(r1), "=r"(r2), "=r"(r3) : "r"(addr))

// fp16 inputs, fp32 accumulate
#define MMA16816F16(c, a, b) \
    asm volatile("mma.sync.aligned.m16n8k16.row.col.f32.f16.f16.f32 " \
        "{%0,%1,%2,%3}, {%4,%5,%6,%7}, {%8,%9}, {%0,%1,%2,%3};" \
        : "+f"((c)[0]), "+f"((c)[1]), "+f"((c)[2]), "+f"((c)[3]) \
        : "r"((a)[0]), "r"((a)[1]), "r"((a)[2]), "r"((a)[3]), \
          "r"((b)[0]), "r"((b)[1]))

// TMA bulk reduce: smem (512B row) -> global row, add.f32, bulk_group completion
#define TMA_REDUCE_ADD_F32(gptr, saddr, bytes) \
    asm volatile("cp.reduce.async.bulk.global.shared::cta.bulk_group.add.f32 " \
        "[%0], [%1], %2;" :: "l"(gptr), "r"(saddr), "r"(bytes) : "memory")
#define BULK_COMMIT() asm volatile("cp.async.bulk.commit_group;" ::: "memory")
#define BULK_WAIT1()  asm volatile("cp.async.bulk.wait_group 1;" ::: "memory")
#define BULK_WAIT0()  asm volatile("cp.async.bulk.wait_group 0;" ::: "memory")
#define FENCE_ASYNC_SHARED() \
    asm volatile("fence.proxy.async.shared::cta;" ::: "memory")

// ============================================================================
// Kernel 1: round x -> fp16 (one pass)
// ============================================================================
__global__ void convert_kernel(const float* __restrict__ x, int n4) {
    int i = blockIdx.x * blockDim.x + threadIdx.x;
    if (i >= n4) return;
    float4 v = reinterpret_cast<const float4*>(x)[i];
    __half2 h0 = __floats2half2_rn(v.x, v.y);
    __half2 h1 = __floats2half2_rn(v.z, v.w);
    reinterpret_cast<uint2*>(g_xh)[i] =
        make_uint2(*(uint32_t*)&h0, *(uint32_t*)&h1);
}

// ============================================================================
// Kernel 2: persistent GEMM via mma.sync, 2-term fp16 split (W split hi/lo)
//   (m_tile, nh): nh=0 -> d_out = x@W1 + b (fp32) ; nh=1 -> g_yh = x@W2 (fp16)
//   (R8-proven shape)
// ============================================================================
#define GT 256
#define AS_OFF(buf)  ((uint32_t)((buf) * 32768))
#define BS_OFF(hl)   ((uint32_t)(65536 + (hl) * 32768))
#define SM_TOTAL     131072

__device__ __forceinline__ void load_A_tile(uint32_t smem_base, int buf,
                                            int node0, int N, int tid) {
#pragma unroll
    for (int i = 0; i < 8; i++) {
        int idx  = tid + (i << 8);
        int row  = idx >> 4;
        int cc   = idx & 15;
        int node = node0 + row;
        uint32_t sz    = (node < N) ? 16u : 0u;
        uint32_t chunk = (uint32_t)(cc ^ (row & 7));
        uint32_t doff  = (uint32_t)row * 256u + chunk * 16u;
        const __half* sh = g_xh + (size_t)node * D + cc * 8;
        CP_ASYNC16(smem_base + AS_OFF(buf) + doff, sh, sz);
    }
}

__global__ __launch_bounds__(GT, 1)
void gemm_kernel(const float* __restrict__ W,
                 const float* __restrict__ bias,
                 float* __restrict__ out,
                 int N) {
    extern __shared__ char smem[];
    uint32_t smem_base = smem_to_u32(smem);
    const int tid  = threadIdx.x;
    const int lane = tid & 31;
    const int wid  = tid >> 5;
    const int warp_m = (wid & 3) << 5;
    const int warp_n = (wid >> 2) << 6;

    const int num_tiles = (N + 127) >> 7;
    const int total = num_tiles * 2;
    int cur_nh = -1;

    int item = blockIdx.x;
    int buf = 0;
    if (item < total) load_A_tile(smem_base, 0, (item % num_tiles) << 7, N, tid);
    CP_COMMIT();

    for (; item < total; item += gridDim.x) {
        const int m_tile = item % num_tiles;
        const int nh     = item / num_tiles;
        const int node0  = m_tile << 7;

        int next = item + gridDim.x;
        if (next < total)
            load_A_tile(smem_base, buf ^ 1, (next % num_tiles) << 7, N, tid);
        CP_COMMIT();

        if (nh != cur_nh) {
            cur_nh = nh;
#pragma unroll
            for (int j = 0; j < 32; j++) {
                int idx = tid + (j << 8);
                int k   = idx >> 6;
                int n   = (idx & 63) << 1;
                const float* wp = W + ((size_t)(nh * 128 + k)) * 128 + n;
                float w0 = wp[0], w1 = wp[1];
                __half2 h = __floats2half2_rn(w0, w1);
                float q0 = w0 - __half2float(__low2half(h));
                float q1 = w1 - __half2float(__high2half(h));
                __half2 l = __floats2half2_rn(q0, q1);
                uint32_t boff = (uint32_t)k * 256u
                              + (uint32_t)(((n >> 3) ^ (k & 7)) << 4)
                              + (uint32_t)((n & 7) << 1);
                *reinterpret_cast<uint32_t*>(smem + BS_OFF(0) + boff) = *(uint32_t*)&h;
                *reinterpret_cast<uint32_t*>(smem + BS_OFF(1) + boff) = *(uint32_t*)&l;
            }
        }

        CP_WAIT1();
        __syncthreads();

        float acc[2][8][4];
#pragma unroll
        for (int mi = 0; mi < 2; mi++)
#pragma unroll
            for (int ni = 0; ni < 8; ni++)
#pragma unroll
                for (int q = 0; q < 4; q++) acc[mi][ni][q] = 0.f;

#pragma unroll
        for (int ks = 0; ks < 8; ks++) {
            uint32_t ah[2][4];
#pragma unroll
            for (int mi = 0; mi < 2; mi++) {
                int row = warp_m + (mi << 4) + (lane & 15);
                int cb  = (ks << 1) + (lane >> 4);
                uint32_t addr = smem_base + AS_OFF(buf)
                              + (uint32_t)row * 256u
                              + (uint32_t)((cb ^ (row & 7)) << 4);
                LDSM_X4(ah[mi][0], ah[mi][1], ah[mi][2], ah[mi][3], addr);
            }
            uint32_t bh[8][2], bl[8][2];
#pragma unroll
            for (int nj = 0; nj < 4; nj++) {
                int row = (ks << 4) + (lane & 15);
                int cb  = (warp_n >> 3) + (nj << 1) + (lane >> 4);
                uint32_t addr = smem_base + BS_OFF(0)
                              + (uint32_t)row * 256u
                              + (uint32_t)((cb ^ (row & 7)) << 4);
                LDSM_X4T(bh[2*nj][0], bh[2*nj][1], bh[2*nj+1][0], bh[2*nj+1][1], addr);
                LDSM_X4T(bl[2*nj][0], bl[2*nj][1], bl[2*nj+1][0], bl[2*nj+1][1],
                         addr + 32768u);
            }
#pragma unroll
            for (int mi = 0; mi < 2; mi++)
#pragma unroll
                for (int ni = 0; ni < 8; ni++) {
                    MMA16816F16(acc[mi][ni], ah[mi], bh[ni]);
                    MMA16816F16(acc[mi][ni], ah[mi], bl[ni]);
                }
        }

        if (nh == 0) {
#pragma unroll
            for (int ni = 0; ni < 8; ni++) {
                int col = warp_n + (ni << 3) + ((lane & 3) << 1);
                float b0 = bias[col], b1 = bias[col + 1];
#pragma unroll
                for (int mi = 0; mi < 2; mi++) {
                    int r = warp_m + (mi << 4) + (lane >> 2);
                    int node = node0 + r;
                    if (node < N) {
                        float2 v = make_float2(acc[mi][ni][0] + b0, acc[mi][ni][1] + b1);
                        *reinterpret_cast<float2*>(out + (size_t)node * D + col) = v;
                    }
                    int node2 = node + 8;
                    if (node2 < N) {
                        float2 v = make_float2(acc[mi][ni][2] + b0, acc[mi][ni][3] + b1);
                        *reinterpret_cast<float2*>(out + (size_t)node2 * D + col) = v;
                    }
                }
            }
        } else {
#pragma unroll
            for (int ni = 0; ni < 8; ni++) {
                int col = warp_n + (ni << 3) + ((lane & 3) << 1);
#pragma unroll
                for (int mi = 0; mi < 2; mi++) {
                    int r = warp_m + (mi << 4) + (lane >> 2);
                    int node = node0 + r;
                    if (node < N) {
                        __half2 v = __floats2half2_rn(acc[mi][ni][0], acc[mi][ni][1]);
                        *reinterpret_cast<__half2*>(g_yh + (size_t)node * D + col) = v;
                    }
                    int node2 = node + 8;
                    if (node2 < N) {
                        __half2 v = __floats2half2_rn(acc[mi][ni][2], acc[mi][ni][3]);
                        *reinterpret_cast<__half2*>(g_yh + (size_t)node2 * D + col) = v;
                    }
                }
            }
        }
        __syncthreads();
        buf ^= 1;
    }
}

// ============================================================================
// Kernel 3: edge scatter via TMA bulk-reduce.
//   Warp processes NE edges: gather fp16 y[src] (coalesced), scale, stage
//   512B in smem, then ONE cp.reduce.async.bulk.add.f32 per edge (TMA engine
//   does the atomic row-add -> no RED wavefronts through L1tex).
//   Double-buffered staging per warp; bulk_group pipelining.
// ============================================================================
#define SC_WARPS 8
#define SC_NE    4     // edges per warp

__global__ __launch_bounds__(SC_WARPS * 32)
void scatter_tma_kernel(const int*   __restrict__ esrc,
                        const int*   __restrict__ edst,
                        const float* __restrict__ eval_,
                        float* __restrict__ out,
                        int E) {
    __shared__ float stage[SC_WARPS][2][128];   // 2 x 512B per warp
    const int lane = threadIdx.x & 31;
    const int wid  = threadIdx.x >> 5;
    const int gw   = blockIdx.x * SC_WARPS + wid;   // global warp id
    const int e0   = gw * SC_NE;

    const uint2* y2 = reinterpret_cast<const uint2*>(g_yh);  // 8B = 4 halves
    uint32_t sa[2];
    sa[0] = smem_to_u32(&stage[wid][0][0]);
    sa[1] = smem_to_u32(&stage[wid][1][0]);

    int issued = 0;
#pragma unroll
    for (int i = 0; i < SC_NE; i++) {
        int e = e0 + i;
        if (e >= E) break;
        int   s = esrc[e];
        int   d = edst[e];
        float v = eval_[e];

        // gather fp16 row (256B coalesced) and scale to fp32
        uint2 w = y2[(size_t)s * 32 + lane];
        float2 f0 = __half22float2(*reinterpret_cast<__half2*>(&w.x));
        float2 f1 = __half22float2(*reinterpret_cast<__half2*>(&w.y));
        float4 r  = make_float4(f0.x * v, f0.y * v, f1.x * v, f1.y * v);

        int buf = i & 1;
        // before reusing this buffer, drain the TMA issued 2 iterations ago
        if (i >= 2) {
            if (lane == 0) BULK_WAIT1();
            __syncwarp();
        }
        *reinterpret_cast<float4*>(&stage[wid][buf][lane * 4]) = r;
        __syncwarp();

        if (lane == 0) {
            FENCE_ASYNC_SHARED();    // order generic STS before async-proxy read
            TMA_REDUCE_ADD_F32(out + (size_t)d * D, sa[buf], 512u);
            BULK_COMMIT();
        }
        issued++;
    }
    // smem must stay alive until the TMA engine has read it
    if (issued > 0 && lane == 0) BULK_WAIT0();
    __syncwarp();
}

// ============================================================================
// Launch
// ============================================================================
extern "C" void kernel_launch(void* const* d_in, const int* in_sizes, int n_in,
                              void* d_out, int out_size) {
    const float* x     = (const float*)d_in[0];
    const int*   esrc  = (const int*)  d_in[1];
    const int*   edst  = (const int*)  d_in[2];
    const float* eval_ = (const float*)d_in[3];
    const float* W     = (const float*)d_in[4];
    const float* bias  = (const float*)d_in[5];
    float*       out   = (float*)d_out;

    const int N = in_sizes[0] / D;     // 100000
    const int E = in_sizes[1];         // 1600000

    // 1) round x -> fp16
    {
        int n4 = N * (D / 4);
        convert_kernel<<<(n4 + 255) / 256, 256>>>(x, n4);
    }
    // 2) persistent GEMM: d_out = x@W1 + b ; g_yh = fp16(x@W2)
    {
        static bool attr_set = false;
        if (!attr_set) {
            cudaFuncSetAttribute(gemm_kernel,
                                 cudaFuncAttributeMaxDynamicSharedMemorySize,
                                 SM_TOTAL);
            attr_set = true;
        }
        gemm_kernel<<<148, GT, SM_TOTAL>>>(W, bias, out, N);
    }
    // 3) scatter via TMA bulk-reduce
    {
        int edges_per_block = SC_WARPS * SC_NE;   // 32
        int blocks = (E + edges_per_block - 1) / edges_per_block;
        scatter_tma_kernel<<<blocks, SC_WARPS * 32>>>(esrc, edst, eval_, out, E);
    }
}

// round 13
// speedup vs baseline: 1.2608x; 1.0498x over previous
#include <cuda_runtime.h>
#include <cuda_fp16.h>
#include <cstdint>

#define D      128      // D_IN = D_OUT
#define NMAX   100000

// Scratch (device globals; no allocation allowed)
__device__ __half g_xh[NMAX * D];   // x rounded to fp16 (GEMM A operand)
__device__ __half g_yh[NMAX * D];   // y = x @ W2, stored fp16

// ============================================================================
// PTX helpers (base ISA: cp.async / ldmatrix / mma.sync / cp.reduce.async.bulk)
// ============================================================================
__device__ __forceinline__ uint32_t smem_to_u32(const void* p) {
    uint32_t a;
    asm("{ .reg .u64 t; cvta.to.shared.u64 t, %1; cvt.u32.u64 %0, t; }"
        : "=r"(a) : "l"(p));
    return a;
}
#define CP_ASYNC16(dst, src, sz) \
    asm volatile("cp.async.cg.shared.global [%0], [%1], 16, %2;" \
        :: "r"(dst), "l"(src), "r"(sz))
#define CP_COMMIT() asm volatile("cp.async.commit_group;" ::: "memory")
#define CP_WAIT1()  asm volatile("cp.async.wait_group 1;"  ::: "memory")

#define LDSM_X4(r0,r1,r2,r3,addr) \
    asm volatile("ldmatrix.sync.aligned.m8n8.x4.shared.b16 {%0,%1,%2,%3}, [%4];" \
        : "=r"(r0), "=r"(r1), "=r"(r2), "=r"(r3) : "r"(addr))
#define LDSM_X4T(r0,r1,r2,r3,addr) \
    asm volatile("ldmatrix.sync.aligned.m8n8.x4.trans.shared.b16 {%0,%1,%2,%3}, [%4];" \
        : "=r"(r0), "=r"(r1), "=r"(r2), "=r"(r3) : "r"(addr))

// fp16 inputs, fp32 accumulate
#define MMA16816F16(c, a, b) \
    asm volatile("mma.sync.aligned.m16n8k16.row.col.f32.f16.f16.f32 " \
        "{%0,%1,%2,%3}, {%4,%5,%6,%7}, {%8,%9}, {%0,%1,%2,%3};" \
        : "+f"((c)[0]), "+f"((c)[1]), "+f"((c)[2]), "+f"((c)[3]) \
        : "r"((a)[0]), "r"((a)[1]), "r"((a)[2]), "r"((a)[3]), \
          "r"((b)[0]), "r"((b)[1]))

// TMA bulk reduce: smem (512B row) -> global row, add.f32, bulk_group completion
#define TMA_REDUCE_ADD_F32(gptr, saddr, bytes) \
    asm volatile("cp.reduce.async.bulk.global.shared::cta.bulk_group.add.f32 " \
        "[%0], [%1], %2;" :: "l"(gptr), "r"(saddr), "r"(bytes) : "memory")
#define BULK_COMMIT() asm volatile("cp.async.bulk.commit_group;" ::: "memory")
#define BULK_WAIT1()  asm volatile("cp.async.bulk.wait_group 1;" ::: "memory")
#define BULK_WAIT0()  asm volatile("cp.async.bulk.wait_group 0;" ::: "memory")
#define FENCE_ASYNC_SHARED() \
    asm volatile("fence.proxy.async.shared::cta;" ::: "memory")

// ============================================================================
// Kernel 1: round x -> fp16 (one pass)
// ============================================================================
__global__ void convert_kernel(const float* __restrict__ x, int n4) {
    int i = blockIdx.x * blockDim.x + threadIdx.x;
    if (i >= n4) return;
    float4 v = reinterpret_cast<const float4*>(x)[i];
    __half2 h0 = __floats2half2_rn(v.x, v.y);
    __half2 h1 = __floats2half2_rn(v.z, v.w);
    reinterpret_cast<uint2*>(g_xh)[i] =
        make_uint2(*(uint32_t*)&h0, *(uint32_t*)&h1);
}

// ============================================================================
// Kernel 2: persistent GEMM via mma.sync, SINGLE-term fp16 (W rounded to fp16)
//   (m_tile, nh): nh=0 -> d_out = x@W1 + b (fp32) ; nh=1 -> g_yh = x@W2 (fp16)
//   SMEM: A double-buffered (2 x 32KB) + B fp16 (32KB) = 96KB.
// ============================================================================
#define GT 256
#define AS_OFF(buf)  ((uint32_t)((buf) * 32768))
#define BS_OFFC      ((uint32_t)65536)
#define SM_TOTAL     98304

__device__ __forceinline__ void load_A_tile(uint32_t smem_base, int buf,
                                            int node0, int N, int tid) {
#pragma unroll
    for (int i = 0; i < 8; i++) {
        int idx  = tid + (i << 8);
        int row  = idx >> 4;
        int cc   = idx & 15;
        int node = node0 + row;
        uint32_t sz    = (node < N) ? 16u : 0u;
        uint32_t chunk = (uint32_t)(cc ^ (row & 7));
        uint32_t doff  = (uint32_t)row * 256u + chunk * 16u;
        const __half* sh = g_xh + (size_t)node * D + cc * 8;
        CP_ASYNC16(smem_base + AS_OFF(buf) + doff, sh, sz);
    }
}

__global__ __launch_bounds__(GT, 1)
void gemm_kernel(const float* __restrict__ W,
                 const float* __restrict__ bias,
                 float* __restrict__ out,
                 int N) {
    extern __shared__ char smem[];
    uint32_t smem_base = smem_to_u32(smem);
    const int tid  = threadIdx.x;
    const int lane = tid & 31;
    const int wid  = tid >> 5;
    const int warp_m = (wid & 3) << 5;
    const int warp_n = (wid >> 2) << 6;

    const int num_tiles = (N + 127) >> 7;
    const int total = num_tiles * 2;
    int cur_nh = -1;

    int item = blockIdx.x;
    int buf = 0;
    if (item < total) load_A_tile(smem_base, 0, (item % num_tiles) << 7, N, tid);
    CP_COMMIT();

    for (; item < total; item += gridDim.x) {
        const int m_tile = item % num_tiles;
        const int nh     = item / num_tiles;
        const int node0  = m_tile << 7;

        int next = item + gridDim.x;
        if (next < total)
            load_A_tile(smem_base, buf ^ 1, (next % num_tiles) << 7, N, tid);
        CP_COMMIT();

        // (re)load B = W[nh*128 : +128][:] rounded to fp16
        if (nh != cur_nh) {
            cur_nh = nh;
#pragma unroll
            for (int j = 0; j < 32; j++) {
                int idx = tid + (j << 8);          // 0..8191 (half2 pairs)
                int k   = idx >> 6;                // 0..127
                int n   = (idx & 63) << 1;         // even col
                const float* wp = W + ((size_t)(nh * 128 + k)) * 128 + n;
                __half2 h = __floats2half2_rn(wp[0], wp[1]);
                uint32_t boff = (uint32_t)k * 256u
                              + (uint32_t)(((n >> 3) ^ (k & 7)) << 4)
                              + (uint32_t)((n & 7) << 1);
                *reinterpret_cast<uint32_t*>(smem + BS_OFFC + boff) = *(uint32_t*)&h;
            }
        }

        CP_WAIT1();
        __syncthreads();

        float acc[2][8][4];
#pragma unroll
        for (int mi = 0; mi < 2; mi++)
#pragma unroll
            for (int ni = 0; ni < 8; ni++)
#pragma unroll
                for (int q = 0; q < 4; q++) acc[mi][ni][q] = 0.f;

#pragma unroll
        for (int ks = 0; ks < 8; ks++) {
            uint32_t ah[2][4];
#pragma unroll
            for (int mi = 0; mi < 2; mi++) {
                int row = warp_m + (mi << 4) + (lane & 15);
                int cb  = (ks << 1) + (lane >> 4);
                uint32_t addr = smem_base + AS_OFF(buf)
                              + (uint32_t)row * 256u
                              + (uint32_t)((cb ^ (row & 7)) << 4);
                LDSM_X4(ah[mi][0], ah[mi][1], ah[mi][2], ah[mi][3], addr);
            }
            uint32_t bh[8][2];
#pragma unroll
            for (int nj = 0; nj < 4; nj++) {
                int row = (ks << 4) + (lane & 15);
                int cb  = (warp_n >> 3) + (nj << 1) + (lane >> 4);
                uint32_t addr = smem_base + BS_OFFC
                              + (uint32_t)row * 256u
                              + (uint32_t)((cb ^ (row & 7)) << 4);
                LDSM_X4T(bh[2*nj][0], bh[2*nj][1], bh[2*nj+1][0], bh[2*nj+1][1], addr);
            }
#pragma unroll
            for (int mi = 0; mi < 2; mi++)
#pragma unroll
                for (int ni = 0; ni < 8; ni++)
                    MMA16816F16(acc[mi][ni], ah[mi], bh[ni]);
        }

        if (nh == 0) {
#pragma unroll
            for (int ni = 0; ni < 8; ni++) {
                int col = warp_n + (ni << 3) + ((lane & 3) << 1);
                float b0 = bias[col], b1 = bias[col + 1];
#pragma unroll
                for (int mi = 0; mi < 2; mi++) {
                    int r = warp_m + (mi << 4) + (lane >> 2);
                    int node = node0 + r;
                    if (node < N) {
                        float2 v = make_float2(acc[mi][ni][0] + b0, acc[mi][ni][1] + b1);
                        *reinterpret_cast<float2*>(out + (size_t)node * D + col) = v;
                    }
                    int node2 = node + 8;
                    if (node2 < N) {
                        float2 v = make_float2(acc[mi][ni][2] + b0, acc[mi][ni][3] + b1);
                        *reinterpret_cast<float2*>(out + (size_t)node2 * D + col) = v;
                    }
                }
            }
        } else {
#pragma unroll
            for (int ni = 0; ni < 8; ni++) {
                int col = warp_n + (ni << 3) + ((lane & 3) << 1);
#pragma unroll
                for (int mi = 0; mi < 2; mi++) {
                    int r = warp_m + (mi << 4) + (lane >> 2);
                    int node = node0 + r;
                    if (node < N) {
                        __half2 v = __floats2half2_rn(acc[mi][ni][0], acc[mi][ni][1]);
                        *reinterpret_cast<__half2*>(g_yh + (size_t)node * D + col) = v;
                    }
                    int node2 = node + 8;
                    if (node2 < N) {
                        __half2 v = __floats2half2_rn(acc[mi][ni][2], acc[mi][ni][3]);
                        *reinterpret_cast<__half2*>(g_yh + (size_t)node2 * D + col) = v;
                    }
                }
            }
        }
        __syncthreads();
        buf ^= 1;
    }
}

// ============================================================================
// Kernel 3: edge scatter via TMA bulk-reduce (R12-proven, unchanged).
// ============================================================================
#define SC_WARPS 8
#define SC_NE    4     // edges per warp

__global__ __launch_bounds__(SC_WARPS * 32)
void scatter_tma_kernel(const int*   __restrict__ esrc,
                        const int*   __restrict__ edst,
                        const float* __restrict__ eval_,
                        float* __restrict__ out,
                        int E) {
    __shared__ float stage[SC_WARPS][2][128];   // 2 x 512B per warp
    const int lane = threadIdx.x & 31;
    const int wid  = threadIdx.x >> 5;
    const int gw   = blockIdx.x * SC_WARPS + wid;   // global warp id
    const int e0   = gw * SC_NE;

    const uint2* y2 = reinterpret_cast<const uint2*>(g_yh);  // 8B = 4 halves
    uint32_t sa[2];
    sa[0] = smem_to_u32(&stage[wid][0][0]);
    sa[1] = smem_to_u32(&stage[wid][1][0]);

    int issued = 0;
#pragma unroll
    for (int i = 0; i < SC_NE; i++) {
        int e = e0 + i;
        if (e >= E) break;
        int   s = esrc[e];
        int   d = edst[e];
        float v = eval_[e];

        // gather fp16 row (256B coalesced) and scale to fp32
        uint2 w = y2[(size_t)s * 32 + lane];
        float2 f0 = __half22float2(*reinterpret_cast<__half2*>(&w.x));
        float2 f1 = __half22float2(*reinterpret_cast<__half2*>(&w.y));
        float4 r  = make_float4(f0.x * v, f0.y * v, f1.x * v, f1.y * v);

        int buf = i & 1;
        // before reusing this buffer, drain the TMA issued 2 iterations ago
        if (i >= 2) {
            if (lane == 0) BULK_WAIT1();
            __syncwarp();
        }
        *reinterpret_cast<float4*>(&stage[wid][buf][lane * 4]) = r;
        __syncwarp();

        if (lane == 0) {
            FENCE_ASYNC_SHARED();    // order generic STS before async-proxy read
            TMA_REDUCE_ADD_F32(out + (size_t)d * D, sa[buf], 512u);
            BULK_COMMIT();
        }
        issued++;
    }
    // smem must stay alive until the TMA engine has read it
    if (issued > 0 && lane == 0) BULK_WAIT0();
    __syncwarp();
}

// ============================================================================
// Launch
// ============================================================================
extern "C" void kernel_launch(void* const* d_in, const int* in_sizes, int n_in,
                              void* d_out, int out_size) {
    const float* x     = (const float*)d_in[0];
    const int*   esrc  = (const int*)  d_in[1];
    const int*   edst  = (const int*)  d_in[2];
    const float* eval_ = (const float*)d_in[3];
    const float* W     = (const float*)d_in[4];
    const float* bias  = (const float*)d_in[5];
    float*       out   = (float*)d_out;

    const int N = in_sizes[0] / D;     // 100000
    const int E = in_sizes[1];         // 1600000

    // 1) round x -> fp16
    {
        int n4 = N * (D / 4);
        convert_kernel<<<(n4 + 255) / 256, 256>>>(x, n4);
    }
    // 2) persistent GEMM: d_out = x@W1 + b ; g_yh = fp16(x@W2)
    {
        static bool attr_set = false;
        if (!attr_set) {
            cudaFuncSetAttribute(gemm_kernel,
                                 cudaFuncAttributeMaxDynamicSharedMemorySize,
                                 SM_TOTAL);
            attr_set = true;
        }
        gemm_kernel<<<148, GT, SM_TOTAL>>>(W, bias, out, N);
    }
    // 3) scatter via TMA bulk-reduce
    {
        int edges_per_block = SC_WARPS * SC_NE;   // 32
        int blocks = (E + edges_per_block - 1) / edges_per_block;
        scatter_tma_kernel<<<blocks, SC_WARPS * 32>>>(esrc, edst, eval_, out, E);
    }
}